// round 6
// baseline (speedup 1.0000x reference)
#include <cuda_runtime.h>
#include <math.h>

#define L     8
#define NH    16
#define DH    64
#define SMAX  2048
#define H     1024
#define FFN   4096
#define ENC   1500
#define VOCAB 8192
#define G     148      // persistent blocks (<= SM count on B300/GB300)
#define T     1024
#define NT    (G * T)
#define ACH   64       // attention key chunks
#define CQ    640      // copy float4s per block per phase slot

// ---------------- device state ----------------
__device__ __align__(16) float g_x[H];
__device__ __align__(16) float g_qkv[3 * H];
__device__ __align__(16) float g_qc[H];
__device__ __align__(16) float g_U[NH * H];
__device__ __align__(16) float g_sc[NH * ENC];
__device__ __align__(16) float g_W[NH * H];
__device__ __align__(16) float g_outc[H];
__device__ __align__(16) float g_ffn[FFN];
__device__ __align__(16) float g_logits[VOCAB];
__device__ __align__(16) float g_pm[NH * ACH];
__device__ __align__(16) float g_ps[NH * ACH];
__device__ __align__(16) float g_po[NH * ACH * DH];
__device__ int g_count = 0;
__device__ volatile int g_gen = 0;
__device__ int g_step_fallback[1] = {512};

// ---------------- grid barrier (all G blocks co-resident) ----------------
__device__ __forceinline__ void gsync() {
    __syncthreads();
    if (threadIdx.x == 0) {
        __threadfence();
        int gen = g_gen;
        if (atomicAdd(&g_count, 1) == G - 1) {
            g_count = 0;
            __threadfence();
            g_gen = gen + 1;
        } else {
            while (g_gen == gen) { __nanosleep(64); }
        }
        __threadfence();
    }
    __syncthreads();
}

// ---------------- block reductions (blockDim = 1024) ----------------
__device__ __forceinline__ float br_sum(float v, float* sb) {
    int tid = threadIdx.x, lane = tid & 31, w = tid >> 5;
#pragma unroll
    for (int o = 16; o; o >>= 1) v += __shfl_down_sync(0xffffffffu, v, o);
    if (lane == 0) sb[w] = v;
    __syncthreads();
    if (tid < 32) {
        float x = sb[tid];
#pragma unroll
        for (int o = 16; o; o >>= 1) x += __shfl_down_sync(0xffffffffu, x, o);
        if (tid == 0) sb[0] = x;
    }
    __syncthreads();
    float r = sb[0];
    __syncthreads();
    return r;
}

__device__ __forceinline__ float br_max(float v, float* sb) {
    int tid = threadIdx.x, lane = tid & 31, w = tid >> 5;
#pragma unroll
    for (int o = 16; o; o >>= 1) v = fmaxf(v, __shfl_down_sync(0xffffffffu, v, o));
    if (lane == 0) sb[w] = v;
    __syncthreads();
    if (tid < 32) {
        float x = sb[tid];
#pragma unroll
        for (int o = 16; o; o >>= 1) x = fmaxf(x, __shfl_down_sync(0xffffffffu, x, o));
        if (tid == 0) sb[0] = x;
    }
    __syncthreads();
    float r = sb[0];
    __syncthreads();
    return r;
}

// ---------------- split-K GEMV core: out[c] += sum_r hs[r] * W[r, c] ----------------
template <int RR>
__device__ __forceinline__ void ph_gemv(const float* __restrict__ W, int n_out, int lognc4,
                                        int K, const float* __restrict__ hs,
                                        float* __restrict__ out, int gt) {
    int nc4 = n_out >> 2;
    int items = (K / RR) << lognc4;
    for (int it = gt; it < items; it += NT) {
        int rc = it >> lognc4;
        int c4 = it & (nc4 - 1);
        const float4* wp = (const float4*)(W + (size_t)rc * RR * n_out) + c4;
        const float* hp = hs + rc * RR;
        float4 acc = make_float4(0.f, 0.f, 0.f, 0.f);
#pragma unroll
        for (int r = 0; r < RR; r++) {
            float4 w = wp[(size_t)r * nc4];
            float a = hp[r];
            acc.x += a * w.x; acc.y += a * w.y; acc.z += a * w.z; acc.w += a * w.w;
        }
        float* o = out + (c4 << 2);
        atomicAdd(o, acc.x); atomicAdd(o + 1, acc.y);
        atomicAdd(o + 2, acc.z); atomicAdd(o + 3, acc.w);
    }
}

// interleaved cache-copy shard (one slot per phase per block)
__device__ __forceinline__ void do_copy(const float4* __restrict__ ck, const float4* __restrict__ cv,
                                        float4* __restrict__ nk, float4* __restrict__ nv,
                                        int step, int bid, int& cp) {
    const size_t half = (size_t)L * NH * SMAX * 16;  // f4 per tensor
    size_t base = ((size_t)cp * G + bid) * CQ;
    cp++;
    int tid = threadIdx.x;
    if (tid < CQ) {
        size_t idx = base + tid;
        if (idx < 2 * half) {
            const float4* src; float4* dst; size_t pos;
            if (idx < half) { src = ck; dst = nk; pos = idx; }
            else            { src = cv; dst = nv; pos = idx - half; }
            int t = (int)((pos >> 4) & (SMAX - 1));
            if (t < step)      dst[pos] = src[pos];
            else if (t > step) dst[pos] = make_float4(0.f, 0.f, 0.f, 0.f);
        }
    }
}

// ---------------- THE persistent kernel ----------------
__global__ void __launch_bounds__(1024, 1)
decoder_kernel(const int* __restrict__ idp, const float* __restrict__ enc,
               const float* __restrict__ ck, const float* __restrict__ cv,
               const int* __restrict__ stepp, const float* __restrict__ cmask,
               const float* __restrict__ tok, const float* __restrict__ pos,
               const float* __restrict__ Wq, const float* __restrict__ Wk,
               const float* __restrict__ Wv, const float* __restrict__ Wo,
               const float* __restrict__ Cq, const float* __restrict__ Ckm,
               const float* __restrict__ Cvm, const float* __restrict__ Co,
               const float* __restrict__ W1, const float* __restrict__ W2,
               const float* __restrict__ ln1g, const float* __restrict__ ln1b,
               const float* __restrict__ ln2g, const float* __restrict__ ln2b,
               const float* __restrict__ ln3g, const float* __restrict__ ln3b,
               const float* __restrict__ lnfg, const float* __restrict__ lnfb,
               const float* __restrict__ Wout,
               float* __restrict__ out, float* __restrict__ nk, float* __restrict__ nv) {
    __shared__ float sm[8192];
    __shared__ float sbr[32];
    __shared__ float mh[4], Sh[4];

    const int tid = threadIdx.x;
    const int bid = blockIdx.x;
    const int gt  = bid * T + tid;
    const int step = stepp[0];
    const int n = step + 1;
    int cp = 0;  // copy slot counter

    const float4* ck4 = (const float4*)ck;
    const float4* cv4 = (const float4*)cv;
    float4* nk4 = (float4*)nk;
    float4* nv4 = (float4*)nv;

    // ---- P0: init ----
    if (bid == 0) {
        int id = idp[0];
        g_x[tid] = tok[(size_t)id * H + tid] + pos[(size_t)step * H + tid];
        for (int i = tid; i < 3 * H; i += T) g_qkv[i] = 0.f;
        for (int i = tid; i < VOCAB; i += T) g_logits[i] = 0.f;
        g_qc[tid] = 0.f;
    }
    do_copy(ck4, cv4, nk4, nv4, step, bid, cp);
    gsync();

    for (int l = 0; l < L; l++) {
        size_t o  = (size_t)l * H * H;
        size_t o1 = (size_t)l * H * FFN;
        size_t o2 = (size_t)l * FFN * H;

        // ---- P1: LN1 + QKV GEMV ----
        {
            float xv = g_x[tid];
            float mean = br_sum(xv, sbr) * (1.f / H);
            float d = xv - mean;
            float rstd = rsqrtf(br_sum(d * d, sbr) * (1.f / H) + 1e-5f);
            sm[tid] = d * rstd * ln1g[l * H + tid] + ln1b[l * H + tid];
            __syncthreads();
            ph_gemv<8>(Wq + o, H, 8, H, sm, g_qkv, gt);
            ph_gemv<8>(Wk + o, H, 8, H, sm, g_qkv + H, gt);
            ph_gemv<8>(Wv + o, H, 8, H, sm, g_qkv + 2 * H, gt);
        }
        do_copy(ck4, cv4, nk4, nv4, step, bid, cp);
        gsync();

        // ---- P2: self-attention partials (warp per (h, chunk)); zero qc ----
        {
            if (gt < H) g_qc[gt] = 0.f;
            int wid = tid >> 5, lane = tid & 31;
            int gw = bid * 32 + wid;
            int cs = (n + ACH - 1) / ACH;
            float* scw = &sm[wid * 32];
            for (int u = gw; u < NH * ACH; u += G * 32) {
                int h = u >> 6, c = u & (ACH - 1);
                int k0 = c * cs, k1 = min(n, k0 + cs), cnt = k1 - k0;
                float* pou = &g_po[u * 64];
                if (cnt <= 0) {
                    ((float2*)pou)[lane] = make_float2(0.f, 0.f);
                    if (lane == 0) { g_pm[u] = -1e30f; g_ps[u] = 0.f; }
                } else {
                    float2 q = ((const float2*)(g_qkv + h * 64))[lane];
                    const float* kbase = ck + (size_t)(l * NH + h) * SMAX * DH;
                    for (int kk = k0; kk < k1; kk++) {
                        const float2* kp = (kk < step) ? (const float2*)(kbase + (size_t)kk * DH)
                                                       : (const float2*)(g_qkv + H + h * 64);
                        float2 kv = kp[lane];
                        float v = kv.x * q.x + kv.y * q.y;
#pragma unroll
                        for (int s = 16; s; s >>= 1) v += __shfl_down_sync(0xffffffffu, v, s);
                        if (lane == 0) scw[kk - k0] = v * 0.125f;
                    }
                    __syncwarp();
                    float sv = (lane < cnt) ? scw[lane] : -1e30f;
                    float m = sv;
#pragma unroll
                    for (int s = 16; s; s >>= 1) m = fmaxf(m, __shfl_xor_sync(0xffffffffu, m, s));
                    float e = (lane < cnt) ? __expf(sv - m) : 0.f;
                    float ssum = e;
#pragma unroll
                    for (int s = 16; s; s >>= 1) ssum += __shfl_xor_sync(0xffffffffu, ssum, s);
                    scw[lane] = e;
                    __syncwarp();
                    const float* vbase = cv + (size_t)(l * NH + h) * SMAX * DH;
                    float2 acc = make_float2(0.f, 0.f);
                    for (int kk = k0; kk < k1; kk++) {
                        const float2* vp = (kk < step) ? (const float2*)(vbase + (size_t)kk * DH)
                                                       : (const float2*)(g_qkv + 2 * H + h * 64);
                        float wgt = scw[kk - k0];
                        float2 v = vp[lane];
                        acc.x += wgt * v.x; acc.y += wgt * v.y;
                    }
                    ((float2*)pou)[lane] = acc;
                    if (lane == 0) { g_pm[u] = m; g_ps[u] = ssum; }
                }
                if (c == 0) {  // write new k/v slot into output caches
                    size_t base = ((size_t)(l * NH + h) * SMAX + step) * DH;
                    ((float2*)(nk + base))[lane] = ((const float2*)(g_qkv + H + h * 64))[lane];
                    ((float2*)(nv + base))[lane] = ((const float2*)(g_qkv + 2 * H + h * 64))[lane];
                }
            }
        }
        do_copy(ck4, cv4, nk4, nv4, step, bid, cp);
        gsync();

        // ---- P3: flash merge -> smem, then Wo GEMV into x ----
        {
            int h = tid >> 6, d = tid & 63;
            float M = -1e30f;
#pragma unroll
            for (int c = 0; c < ACH; c++) M = fmaxf(M, g_pm[h * ACH + c]);
            float S = 0.f, ov = 0.f;
#pragma unroll
            for (int c = 0; c < ACH; c++) {
                float e = __expf(g_pm[h * ACH + c] - M);
                S += g_ps[h * ACH + c] * e;
                ov += e * g_po[(h * ACH + c) * 64 + d];
            }
            sm[tid] = ov / S;
            __syncthreads();
            ph_gemv<8>(Wo + o, H, 8, H, sm, g_x, gt);
        }
        do_copy(ck4, cv4, nk4, nv4, step, bid, cp);
        gsync();

        // ---- P4: LN2 + Cq GEMV -> qc ----
        {
            float xv = g_x[tid];
            float mean = br_sum(xv, sbr) * (1.f / H);
            float d = xv - mean;
            float rstd = rsqrtf(br_sum(d * d, sbr) * (1.f / H) + 1e-5f);
            sm[tid] = d * rstd * ln2g[l * H + tid] + ln2b[l * H + tid];
            __syncthreads();
            ph_gemv<8>(Cq + o, H, 8, H, sm, g_qc, gt);
        }
        do_copy(ck4, cv4, nk4, nv4, step, bid, cp);
        gsync();

        // ---- P5: U[h][i] = Ck[i, h*64:]. qc[h]; zero g_W ----
        {
            if (gt < NH * H) g_W[gt] = 0.f;
            sm[tid] = g_qc[tid];
            __syncthreads();
            int ltid = tid & 255;
            float4 q4 = ((const float4*)sm)[ltid];
            int h = ltid >> 4;
            for (int u = bid * 4 + (tid >> 8); u < H / 8; u += G * 4) {
#pragma unroll
                for (int r = 0; r < 8; r++) {
                    int i = u * 8 + r;
                    float4 w = ((const float4*)(Ckm + o + (size_t)i * H))[ltid];
                    float v = w.x * q4.x + w.y * q4.y + w.z * q4.z + w.w * q4.w;
                    v += __shfl_down_sync(0xffffffffu, v, 8);
                    v += __shfl_down_sync(0xffffffffu, v, 4);
                    v += __shfl_down_sync(0xffffffffu, v, 2);
                    v += __shfl_down_sync(0xffffffffu, v, 1);
                    if ((ltid & 15) == 0) g_U[h * H + i] = v;
                }
            }
        }
        do_copy(ck4, cv4, nk4, nv4, step, bid, cp);
        gsync();

        // ---- P6: scores[h][f] = enc[f].U[h]*scale + cmask (U halves in smem); zero outc ----
        {
            if (gt < H) g_outc[gt] = 0.f;
            int wid = tid >> 5, lane = tid & 31;
            for (int p = 0; p < 2; p++) {
                __syncthreads();
                for (int i = tid; i < 8 * H; i += T) sm[i] = g_U[p * 8 * H + i];
                __syncthreads();
                for (int f = bid * 32 + wid; f < ENC; f += G * 32) {
                    const float4* ep = (const float4*)(enc + (size_t)f * H);
                    float cm = cmask[f];
#pragma unroll
                    for (int h = 0; h < 8; h++) {
                        const float4* up = ((const float4*)sm) + h * 256;
                        float acc = 0.f;
#pragma unroll
                        for (int j = 0; j < 8; j++) {
                            float4 e = ep[lane + 32 * j];
                            float4 u = up[lane + 32 * j];
                            acc += e.x * u.x + e.y * u.y + e.z * u.z + e.w * u.w;
                        }
#pragma unroll
                        for (int s = 16; s; s >>= 1) acc += __shfl_down_sync(0xffffffffu, acc, s);
                        if (lane == 0) g_sc[(p * 8 + h) * ENC + f] = acc * 0.125f + cm;
                    }
                }
            }
        }
        do_copy(ck4, cv4, nk4, nv4, step, bid, cp);
        gsync();

        // ---- P7: wsum with on-the-fly softmax (blocks < 128) ----
        if (bid < 128) {
            int hg = bid >> 5, fc = bid & 31;
            for (int hh = 0; hh < 4; hh++) {
                int h = hg * 4 + hh;
                float m = -1e30f;
                for (int i = tid; i < ENC; i += T) m = fmaxf(m, g_sc[h * ENC + i]);
                m = br_max(m, sbr);
                float s = 0.f;
                for (int i = tid; i < ENC; i += T) s += __expf(g_sc[h * ENC + i] - m);
                s = br_sum(s, sbr);
                if (tid == 0) { mh[hh] = m; Sh[hh] = s; }
            }
            __syncthreads();
            for (int idx = tid; idx < 4 * 48; idx += T) {
                int hh = idx / 48, k = idx - hh * 48;
                int f = fc * 48 + k;
                sm[idx] = (f < ENC) ? __expf(g_sc[(hg * 4 + hh) * ENC + f] - mh[hh]) / Sh[hh] : 0.f;
            }
            __syncthreads();
            int hh = tid >> 8, c4 = tid & 255;
            float4 acc = make_float4(0.f, 0.f, 0.f, 0.f);
            int fend = min(48, ENC - fc * 48);
            for (int k = 0; k < fend; k++) {
                float4 e = ((const float4*)(enc + (size_t)(fc * 48 + k) * H))[c4];
                float a = sm[hh * 48 + k];
                acc.x += a * e.x; acc.y += a * e.y; acc.z += a * e.z; acc.w += a * e.w;
            }
            float* op = &g_W[(hg * 4 + hh) * H + (c4 << 2)];
            atomicAdd(op, acc.x); atomicAdd(op + 1, acc.y);
            atomicAdd(op + 2, acc.z); atomicAdd(op + 3, acc.w);
        }
        do_copy(ck4, cv4, nk4, nv4, step, bid, cp);
        gsync();

        // ---- P8: outc[col] += sum_i W[h(col), i] * Cv[i, col]; zero ffn ----
        {
            if (gt < FFN) g_ffn[gt] = 0.f;
            for (int it = gt; it < (H / 8) * 256; it += NT) {
                int rc = it >> 8, c4 = it & 255;
                int h = c4 >> 4;
                float4 acc = make_float4(0.f, 0.f, 0.f, 0.f);
#pragma unroll
                for (int r = 0; r < 8; r++) {
                    int i = rc * 8 + r;
                    float wv = g_W[h * H + i];
                    float4 cvv = ((const float4*)(Cvm + o + (size_t)i * H))[c4];
                    acc.x += wv * cvv.x; acc.y += wv * cvv.y;
                    acc.z += wv * cvv.z; acc.w += wv * cvv.w;
                }
                float* op = &g_outc[c4 << 2];
                atomicAdd(op, acc.x); atomicAdd(op + 1, acc.y);
                atomicAdd(op + 2, acc.z); atomicAdd(op + 3, acc.w);
            }
        }
        do_copy(ck4, cv4, nk4, nv4, step, bid, cp);
        gsync();

        // ---- P9: Co GEMV into x; zero qkv ----
        {
            sm[tid] = g_outc[tid];
            __syncthreads();
            ph_gemv<8>(Co + o, H, 8, H, sm, g_x, gt);
            if (gt < 3 * H) g_qkv[gt] = 0.f;
        }
        do_copy(ck4, cv4, nk4, nv4, step, bid, cp);
        gsync();

        // ---- P10: LN3 + W1 GEMV -> ffn ----
        {
            float xv = g_x[tid];
            float mean = br_sum(xv, sbr) * (1.f / H);
            float d = xv - mean;
            float rstd = rsqrtf(br_sum(d * d, sbr) * (1.f / H) + 1e-5f);
            sm[tid] = d * rstd * ln3g[l * H + tid] + ln3b[l * H + tid];
            __syncthreads();
            ph_gemv<16>(W1 + o1, FFN, 10, H, sm, g_ffn, gt);
        }
        do_copy(ck4, cv4, nk4, nv4, step, bid, cp);
        gsync();

        // ---- P11: relu + W2 GEMV into x ----
        {
            for (int i = tid; i < FFN; i += T) sm[i] = fmaxf(g_ffn[i], 0.f);
            __syncthreads();
            ph_gemv<16>(W2 + o2, H, 8, FFN, sm, g_x, gt);
        }
        do_copy(ck4, cv4, nk4, nv4, step, bid, cp);
        gsync();
    }

    // ---- P12: LNf + Wout GEMV -> logits ----
    {
        float xv = g_x[tid];
        float mean = br_sum(xv, sbr) * (1.f / H);
        float d = xv - mean;
        float rstd = rsqrtf(br_sum(d * d, sbr) * (1.f / H) + 1e-5f);
        sm[tid] = d * rstd * lnfg[tid] + lnfb[tid];
        __syncthreads();
        ph_gemv<16>(Wout, VOCAB, 11, H, sm, g_logits, gt);
    }
    do_copy(ck4, cv4, nk4, nv4, step, bid, cp);
    gsync();

    // ---- P13: log-softmax (block 0); final copy shard for all ----
    do_copy(ck4, cv4, nk4, nv4, step, bid, cp);
    if (bid == 0) {
        float m = -1e30f;
        for (int i = tid; i < VOCAB; i += T) m = fmaxf(m, g_logits[i]);
        m = br_max(m, sbr);
        float s = 0.f;
        for (int i = tid; i < VOCAB; i += T) s += __expf(g_logits[i] - m);
        s = br_sum(s, sbr);
        float ls = logf(s);
        for (int i = tid; i < VOCAB; i += T) out[i] = g_logits[i] - m - ls;
    }
}

// ---------------- host ----------------
extern "C" void kernel_launch(void* const* d_in, const int* in_sizes, int n_in,
                              void* d_out, int out_size) {
    int has_step = (n_in >= 27) ? 1 : 0;
    int idx = 0;
    const int*   input_id = (const int*)d_in[idx++];
    const float* enc      = (const float*)d_in[idx++];
    const float* ck       = (const float*)d_in[idx++];
    const float* cv       = (const float*)d_in[idx++];
    const int*   stepp    = nullptr;
    if (has_step) stepp = (const int*)d_in[idx++];
    const float* cmask = (const float*)d_in[idx++];
    const float* tok   = (const float*)d_in[idx++];
    const float* pos   = (const float*)d_in[idx++];
    const float* Wq = (const float*)d_in[idx++];
    const float* Wk = (const float*)d_in[idx++];
    const float* Wv = (const float*)d_in[idx++];
    const float* Wo = (const float*)d_in[idx++];
    const float* Cq = (const float*)d_in[idx++];
    const float* Ck = (const float*)d_in[idx++];
    const float* Cv = (const float*)d_in[idx++];
    const float* Co = (const float*)d_in[idx++];
    const float* W1 = (const float*)d_in[idx++];
    const float* W2 = (const float*)d_in[idx++];
    const float* ln1g = (const float*)d_in[idx++];
    const float* ln1b = (const float*)d_in[idx++];
    const float* ln2g = (const float*)d_in[idx++];
    const float* ln2b = (const float*)d_in[idx++];
    const float* ln3g = (const float*)d_in[idx++];
    const float* ln3b = (const float*)d_in[idx++];
    const float* lnfg = (const float*)d_in[idx++];
    const float* lnfb = (const float*)d_in[idx++];
    const float* Wout = (const float*)d_in[idx++];

    if (!stepp) {
        void* p;
        cudaGetSymbolAddress(&p, g_step_fallback);
        stepp = (const int*)p;
    }

    float* out = (float*)d_out;
    float* nk = out + VOCAB;
    float* nv = nk + (size_t)L * NH * SMAX * DH;

    decoder_kernel<<<G, T>>>(input_id, enc, ck, cv, stepp, cmask, tok, pos,
                             Wq, Wk, Wv, Wo, Cq, Ck, Cv, Co, W1, W2,
                             ln1g, ln1b, ln2g, ln2b, ln3g, ln3b, lnfg, lnfb,
                             Wout, out, nk, nv);
}

// round 7
// speedup vs baseline: 1.5347x; 1.5347x over previous
#include <cuda_runtime.h>
#include <cuda_bf16.h>
#include <math.h>

#define L     8
#define NH    16
#define DH    64
#define SMAX  2048
#define H     1024
#define FFN   4096
#define ENC   1500
#define VOCAB 8192
#define FCH   48   // enc f-rows per k_wsum chunk (32*48 >= 1500)
#define CH    8    // attention key chunks (R3 value)

// ---------------- device state ----------------
__device__ __align__(16) float g_x[H];
__device__ __align__(16) float g_qkv[3 * H];
__device__ __align__(16) float g_qc[H];
__device__ __align__(16) float g_U[NH * H];       // U[h][i] (transposed)
__device__ __align__(16) float g_sc[NH * ENC];
__device__ __align__(16) float g_W[NH * H];
__device__ __align__(16) float g_outc[H];
__device__ __align__(16) float g_ffn[FFN];
__device__ __align__(16) float g_logits[VOCAB];
__device__ float g_pm[NH * CH];
__device__ float g_ps[NH * CH];
__device__ __align__(16) float g_po[NH * CH * DH];
__device__ int   g_step_fallback[1] = {512};

// ---------------- block reductions ----------------
__device__ __forceinline__ float br_sum(float v, float* sb) {
    int tid = threadIdx.x, lane = tid & 31, w = tid >> 5;
#pragma unroll
    for (int o = 16; o; o >>= 1) v += __shfl_down_sync(0xffffffffu, v, o);
    if (lane == 0) sb[w] = v;
    __syncthreads();
    if (tid < 32) {
        int nw = (blockDim.x + 31) >> 5;
        float x = (tid < nw) ? sb[tid] : 0.0f;
#pragma unroll
        for (int o = 16; o; o >>= 1) x += __shfl_down_sync(0xffffffffu, x, o);
        if (tid == 0) sb[0] = x;
    }
    __syncthreads();
    float r = sb[0];
    __syncthreads();
    return r;
}

__device__ __forceinline__ float br_max(float v, float* sb) {
    int tid = threadIdx.x, lane = tid & 31, w = tid >> 5;
#pragma unroll
    for (int o = 16; o; o >>= 1) v = fmaxf(v, __shfl_down_sync(0xffffffffu, v, o));
    if (lane == 0) sb[w] = v;
    __syncthreads();
    if (tid < 32) {
        int nw = (blockDim.x + 31) >> 5;
        float x = (tid < nw) ? sb[tid] : -1e30f;
#pragma unroll
        for (int o = 16; o; o >>= 1) x = fmaxf(x, __shfl_down_sync(0xffffffffu, x, o));
        if (tid == 0) sb[0] = x;
    }
    __syncthreads();
    float r = sb[0];
    __syncthreads();
    return r;
}

__device__ __forceinline__ void ln_stats(float* sb, float& mean, float& rstd) {
    int tid = threadIdx.x;
    float s = 0.f;
    for (int i = tid; i < H; i += blockDim.x) s += g_x[i];
    mean = br_sum(s, sb) * (1.0f / H);
    float v = 0.f;
    for (int i = tid; i < H; i += blockDim.x) { float d = g_x[i] - mean; v += d * d; }
    rstd = rsqrtf(br_sum(v, sb) * (1.0f / H) + 1e-5f);
}

// ---------------- kernels ----------------

// persistent grid-stride cache copy (40 blocks -> bounded SM contention)
__global__ void k_copy_p(const float4* __restrict__ ck, const float4* __restrict__ cv,
                         float4* __restrict__ nk, float4* __restrict__ nv,
                         const int* __restrict__ stepp) {
    int step = stepp[0];
    const size_t half = (size_t)L * NH * SMAX * 16;  // float4 per tensor
    const size_t total = 2 * half;
    size_t stride = (size_t)gridDim.x * blockDim.x;
    for (size_t idx = (size_t)blockIdx.x * blockDim.x + threadIdx.x; idx < total; idx += stride) {
        const float4* src; float4* dst; size_t pos;
        if (idx < half) { src = ck; dst = nk; pos = idx; }
        else            { src = cv; dst = nv; pos = idx - half; }
        int t = (int)((pos >> 4) & (SMAX - 1));
        if (t < step)      dst[pos] = src[pos];
        else if (t > step) dst[pos] = make_float4(0.f, 0.f, 0.f, 0.f);
    }
}

// x = tok_emb[id] + pos_emb[step]; zero qkv
__global__ void k_init(const int* __restrict__ idp, const int* __restrict__ stepp,
                       const float* __restrict__ tok, const float* __restrict__ pos) {
    int tid = threadIdx.x;  // 1024
    int id = idp[0], st = stepp[0];
    g_x[tid] = tok[(size_t)id * H + tid] + pos[(size_t)st * H + tid];
    for (int i = tid; i < 3 * H; i += 1024) g_qkv[i] = 0.f;
}

// qkv += LN1(x) @ [Wq|Wk|Wv], split-K 16 rows (grid: 12 x 64, block 256) [R3]
__global__ void k_gemv3_ln(const float* __restrict__ Wq, const float* __restrict__ Wk,
                           const float* __restrict__ Wv,
                           const float* __restrict__ g, const float* __restrict__ b) {
    __shared__ float sb[32];
    __shared__ float hc[16];
    int tid = threadIdx.x;
    float mean, rstd;
    ln_stats(sb, mean, rstd);
    int i0 = blockIdx.y * 16;
    if (tid < 16) { int i = i0 + tid; hc[tid] = (g_x[i] - mean) * rstd * g[i] + b[i]; }
    __syncthreads();
    int j = blockIdx.x * 256 + tid;  // 0..3071
    const float* Wm = (j < H) ? Wq : ((j < 2 * H) ? Wk : Wv);
    int jj = j & (H - 1);
    float acc = 0.f;
#pragma unroll
    for (int r = 0; r < 16; r++) acc += hc[r] * Wm[(size_t)(i0 + r) * H + jj];
    atomicAdd(&g_qkv[j], acc);
}

// out += LN(x; g,b) @ W  (grid: n_out/256 x 64, block 256) [R3]
__global__ void k_gemv_ln(const float* __restrict__ Wm,
                          const float* __restrict__ g, const float* __restrict__ b,
                          float* __restrict__ out, int n_out) {
    __shared__ float sb[32];
    __shared__ float hc[16];
    int tid = threadIdx.x;
    float mean, rstd;
    ln_stats(sb, mean, rstd);
    int i0 = blockIdx.y * 16;
    if (tid < 16) { int i = i0 + tid; hc[tid] = (g_x[i] - mean) * rstd * g[i] + b[i]; }
    __syncthreads();
    int j = blockIdx.x * 256 + tid;
    float acc = 0.f;
#pragma unroll
    for (int r = 0; r < 16; r++) acc += hc[r] * Wm[(size_t)(i0 + r) * n_out + j];
    atomicAdd(&out[j], acc);
}

// out += (relu?)a @ W  (grid: n_out/256 x n_in/16, block 256) + zero 2 buffers [R3]
__global__ void k_gemv_plain(const float* __restrict__ Wm, const float* __restrict__ a,
                             float* __restrict__ out, int n_out, int relu,
                             float* z1, int zn1, float* z2, int zn2) {
    __shared__ float ac[16];
    int tid = threadIdx.x;
    int gt = (blockIdx.y * gridDim.x + blockIdx.x) * blockDim.x + tid;
    int T = gridDim.x * gridDim.y * blockDim.x;
    for (int k = gt; k < zn1; k += T) z1[k] = 0.f;
    for (int k = gt; k < zn2; k += T) z2[k] = 0.f;
    int i0 = blockIdx.y * 16;
    if (tid < 16) { float x = a[i0 + tid]; if (relu) x = fmaxf(x, 0.f); ac[tid] = x; }
    __syncthreads();
    int j = blockIdx.x * 256 + tid;
    float acc = 0.f;
#pragma unroll
    for (int r = 0; r < 16; r++) acc += ac[r] * Wm[(size_t)(i0 + r) * n_out + j];
    atomicAdd(&out[j], acc);
}

// x += merge(attn partials) @ Wo  (grid: 4 x 64, block 256); zeros g_qc
__global__ void k_gemv_merge(const float* __restrict__ Wm, float* __restrict__ out) {
    __shared__ float ac[16];
    int tid = threadIdx.x;
    int gt = (blockIdx.y * gridDim.x + blockIdx.x) * 256 + tid;
    int T = gridDim.x * gridDim.y * 256;
    for (int k = gt; k < H; k += T) g_qc[k] = 0.f;
    int i0 = blockIdx.y * 16;
    if (tid < 16) {
        int i = i0 + tid;
        int h = i >> 6, d = i & 63;
        float M = -1e30f;
#pragma unroll
        for (int c = 0; c < CH; c++) M = fmaxf(M, g_pm[h * CH + c]);
        float S = 0.f, o = 0.f;
#pragma unroll
        for (int c = 0; c < CH; c++) {
            float e = __expf(g_pm[h * CH + c] - M);
            S += g_ps[h * CH + c] * e;
            o += e * g_po[(h * CH + c) * 64 + d];
        }
        ac[tid] = o / S;
    }
    __syncthreads();
    int j = blockIdx.x * 256 + tid;
    float acc = 0.f;
#pragma unroll
    for (int r = 0; r < 16; r++) acc += ac[r] * Wm[(size_t)(i0 + r) * H + j];
    atomicAdd(&out[j], acc);
}

// flash-decode partials with smem-staged K tiles (coalesced): grid (16, 8), block 256
__global__ void k_attn_part(const float* __restrict__ ck, const float* __restrict__ cv,
                            float* __restrict__ nk, float* __restrict__ nv,
                            const int* __restrict__ stepp, int l) {
    __shared__ float4 Ks[64 * 16];   // 64 keys x 64 floats (16KB)
    __shared__ float4 qs4[16];
    __shared__ float sc[256];
    __shared__ float sb[32];
    __shared__ float red[256];
    int tid = threadIdx.x;
    int h = blockIdx.x, c = blockIdx.y;
    int step = stepp[0];
    int n = step + 1;
    int cs = (n + CH - 1) / CH;
    int k0 = c * cs;
    int k1 = min(n, k0 + cs);
    int cnt = k1 - k0;
    if (tid < 16) qs4[tid] = ((const float4*)&g_qkv[h * 64])[tid];
    const float* kbase = ck + (size_t)(l * NH + h) * SMAX * DH;
    // write new k/v cache slot once (chunk 0 blocks)
    if (c == 0 && tid >= 128 && tid < 256) {
        int t2 = tid - 128;
        size_t base = ((size_t)(l * NH + h) * SMAX + step) * DH;
        if (t2 < 64) nk[base + t2]      = g_qkv[H + h * 64 + t2];
        else         nv[base + t2 - 64] = g_qkv[2 * H + h * 64 + t2 - 64];
    }
    // scoring: stage 64-key tiles into smem (coalesced), dot from smem
    for (int t0 = 0; t0 < cnt; t0 += 64) {
        int tcnt = min(64, cnt - t0);
        __syncthreads();
        for (int i = tid; i < tcnt * 16; i += 256) {
            int r = i >> 4, col = i & 15;
            int kk = k0 + t0 + r;
            const float4* kp = (kk < step) ? (const float4*)(kbase + (size_t)kk * DH)
                                           : (const float4*)(&g_qkv[H + h * 64]);
            Ks[r * 16 + col] = kp[col];
        }
        __syncthreads();
        if (tid < tcnt) {
            float acc = 0.f;
#pragma unroll
            for (int jj = 0; jj < 16; jj++) {
                int j = (tid + jj) & 15;   // bank rotation
                float4 kv = Ks[tid * 16 + j];
                float4 q = qs4[j];
                acc += kv.x * q.x + kv.y * q.y + kv.z * q.z + kv.w * q.w;
            }
            sc[t0 + tid] = acc * 0.125f;
        }
    }
    __syncthreads();
    // chunk softmax
    float m = -1e30f;
    for (int i = tid; i < cnt; i += 256) m = fmaxf(m, sc[i]);
    m = br_max(m, sb);
    float s = 0.f;
    for (int i = tid; i < cnt; i += 256) { float e = __expf(sc[i] - m); sc[i] = e; s += e; }
    s = br_sum(s, sb);
    // V pass (coalesced)
    int d = tid & 63, part = tid >> 6;
    const float* vbase = cv + (size_t)(l * NH + h) * SMAX * DH;
    float acc = 0.f;
    for (int kk = k0 + part; kk < k1; kk += 4) {
        const float* vp = (kk < step) ? (vbase + (size_t)kk * DH) : (&g_qkv[2 * H + h * 64]);
        acc += sc[kk - k0] * vp[d];
    }
    red[tid] = acc;
    __syncthreads();
    if (part == 0) {
        float o = red[d] + red[64 + d] + red[128 + d] + red[192 + d];
        g_po[(h * CH + c) * 64 + d] = o;
        if (d == 0) { g_pm[h * CH + c] = m; g_ps[h * CH + c] = s; }
    }
}

// U[h][i]: grid 128, block 256; float4 loads, 16-lane segmented reduce [R3]
__global__ void k_U(const float* __restrict__ Ck) {
    __shared__ float4 qs[256];
    int tid = threadIdx.x;
    qs[tid] = ((const float4*)g_qc)[tid];
    __syncthreads();
    float4 q = qs[tid];
    int i0 = blockIdx.x * 8;
    int h = tid >> 4;
#pragma unroll
    for (int r = 0; r < 8; r++) {
        int i = i0 + r;
        float4 w = ((const float4*)(Ck + (size_t)i * H))[tid];
        float v = w.x * q.x + w.y * q.y + w.z * q.z + w.w * q.w;
        v += __shfl_down_sync(0xffffffffu, v, 8);
        v += __shfl_down_sync(0xffffffffu, v, 4);
        v += __shfl_down_sync(0xffffffffu, v, 2);
        v += __shfl_down_sync(0xffffffffu, v, 1);
        if ((tid & 15) == 0) g_U[h * H + i] = v;
    }
}

// scores: grid 188, block 512 (warp = head), U register-resident [R3]
__global__ void k_scores(const float* __restrict__ enc, const float* __restrict__ cmask) {
    int w = threadIdx.x >> 5, lane = threadIdx.x & 31;
    const float4* up = (const float4*)(g_U + w * H);
    float4 u[8];
#pragma unroll
    for (int j = 0; j < 8; j++) u[j] = up[lane + 32 * j];
#pragma unroll
    for (int ff = 0; ff < 8; ff++) {
        int f = blockIdx.x * 8 + ff;
        if (f >= ENC) break;
        const float4* ep = (const float4*)(enc + (size_t)f * H);
        float acc = 0.f;
#pragma unroll
        for (int j = 0; j < 8; j++) {
            float4 e = ep[lane + 32 * j];
            acc += e.x * u[j].x + e.y * u[j].y + e.z * u[j].z + e.w * u[j].w;
        }
#pragma unroll
        for (int o = 16; o; o >>= 1) acc += __shfl_down_sync(0xffffffffu, acc, o);
        if (lane == 0) g_sc[w * ENC + f] = acc * 0.125f + cmask[f];
    }
}

// per-head softmax; zero g_W and g_outc. grid 16, block 256 [R3]
__global__ void k_softmax16() {
    __shared__ float sb[32];
    int h = blockIdx.x, tid = threadIdx.x;
    float* row = &g_sc[h * ENC];
    float m = -1e30f;
    for (int i = tid; i < ENC; i += 256) m = fmaxf(m, row[i]);
    m = br_max(m, sb);
    float s = 0.f;
    for (int i = tid; i < ENC; i += 256) { float e = __expf(row[i] - m); row[i] = e; s += e; }
    s = br_sum(s, sb);
    float inv = 1.f / s;
    for (int i = tid; i < ENC; i += 256) row[i] *= inv;
    for (int i = tid; i < H; i += 256) g_W[h * H + i] = 0.f;
    if (h == 0) for (int i = tid; i < H; i += 256) g_outc[i] = 0.f;
}

// W[h][cols] += attc @ enc. grid (4 head-groups, 32 f-chunks), block 256 [R3]
__global__ void k_wsum(const float* __restrict__ enc) {
    __shared__ float at[4 * FCH];
    int tid = threadIdx.x, fc = blockIdx.y, hg = blockIdx.x;
    for (int idx = tid; idx < 4 * FCH; idx += 256) {
        int hh = idx / FCH, k = idx % FCH;
        int f = fc * FCH + k;
        at[idx] = (f < ENC) ? g_sc[(hg * 4 + hh) * ENC + f] : 0.f;
    }
    __syncthreads();
    int c0 = tid * 4;
    float4 acc[4];
#pragma unroll
    for (int hh = 0; hh < 4; hh++) acc[hh] = make_float4(0.f, 0.f, 0.f, 0.f);
    int fend = min(FCH, ENC - fc * FCH);
    for (int k = 0; k < fend; k++) {
        float4 e = *(const float4*)(enc + (size_t)(fc * FCH + k) * H + c0);
#pragma unroll
        for (int hh = 0; hh < 4; hh++) {
            float a = at[hh * FCH + k];
            acc[hh].x += a * e.x; acc[hh].y += a * e.y;
            acc[hh].z += a * e.z; acc[hh].w += a * e.w;
        }
    }
#pragma unroll
    for (int hh = 0; hh < 4; hh++) {
        float* o = &g_W[(hg * 4 + hh) * H + c0];
        atomicAdd(o, acc[hh].x); atomicAdd(o + 1, acc[hh].y);
        atomicAdd(o + 2, acc[hh].z); atomicAdd(o + 3, acc[hh].w);
    }
}

// outc[col] += sum_i W[h(col),i]*Cv[i,col]; zero g_ffn. grid 128, block 256 [R3]
__global__ void k_outc(const float* __restrict__ Cv) {
    int tid = threadIdx.x;
    int c0 = tid * 4;
    int h = tid >> 4;
    int i0 = blockIdx.x * 8;
    float4 acc = make_float4(0.f, 0.f, 0.f, 0.f);
#pragma unroll
    for (int r = 0; r < 8; r++) {
        int i = i0 + r;
        float wv = g_W[h * H + i];
        float4 cv4 = *(const float4*)(Cv + (size_t)i * H + c0);
        acc.x += wv * cv4.x; acc.y += wv * cv4.y;
        acc.z += wv * cv4.z; acc.w += wv * cv4.w;
    }
    float* o = &g_outc[c0];
    atomicAdd(o, acc.x); atomicAdd(o + 1, acc.y);
    atomicAdd(o + 2, acc.z); atomicAdd(o + 3, acc.w);
    int gt = blockIdx.x * 256 + tid;
    if (gt < FFN) g_ffn[gt] = 0.f;
}

__global__ void k_logsoftmax(float* __restrict__ out) {
    __shared__ float sb[32];
    int tid = threadIdx.x;
    float m = -1e30f;
    for (int i = tid; i < VOCAB; i += 256) m = fmaxf(m, g_logits[i]);
    m = br_max(m, sb);
    float s = 0.f;
    for (int i = tid; i < VOCAB; i += 256) s += __expf(g_logits[i] - m);
    s = br_sum(s, sb);
    float ls = logf(s);
    for (int i = tid; i < VOCAB; i += 256) out[i] = g_logits[i] - m - ls;
}

// ---------------- host ----------------
extern "C" void kernel_launch(void* const* d_in, const int* in_sizes, int n_in,
                              void* d_out, int out_size) {
    int has_step = (n_in >= 27) ? 1 : 0;
    int idx = 0;
    const int*   input_id = (const int*)d_in[idx++];
    const float* enc      = (const float*)d_in[idx++];
    const float* ck       = (const float*)d_in[idx++];
    const float* cv       = (const float*)d_in[idx++];
    const int*   stepp    = nullptr;
    if (has_step) stepp = (const int*)d_in[idx++];
    const float* cmask = (const float*)d_in[idx++];
    const float* tok   = (const float*)d_in[idx++];
    const float* pos   = (const float*)d_in[idx++];
    const float* Wq = (const float*)d_in[idx++];
    const float* Wk = (const float*)d_in[idx++];
    const float* Wv = (const float*)d_in[idx++];
    const float* Wo = (const float*)d_in[idx++];
    const float* Cq = (const float*)d_in[idx++];
    const float* Ck = (const float*)d_in[idx++];
    const float* Cv = (const float*)d_in[idx++];
    const float* Co = (const float*)d_in[idx++];
    const float* W1 = (const float*)d_in[idx++];
    const float* W2 = (const float*)d_in[idx++];
    const float* ln1g = (const float*)d_in[idx++];
    const float* ln1b = (const float*)d_in[idx++];
    const float* ln2g = (const float*)d_in[idx++];
    const float* ln2b = (const float*)d_in[idx++];
    const float* ln3g = (const float*)d_in[idx++];
    const float* ln3b = (const float*)d_in[idx++];
    const float* lnfg = (const float*)d_in[idx++];
    const float* lnfb = (const float*)d_in[idx++];
    const float* Wout = (const float*)d_in[idx++];

    if (!stepp) {
        void* p;
        cudaGetSymbolAddress(&p, g_step_fallback);
        stepp = (const int*)p;
    }

    float* out = (float*)d_out;
    float* nk = out + VOCAB;
    float* nv = nk + (size_t)L * NH * SMAX * DH;

    float *p_x, *p_qc, *p_outc, *p_ffn, *p_logits, *p_qkv;
    cudaGetSymbolAddress((void**)&p_x, g_x);
    cudaGetSymbolAddress((void**)&p_qc, g_qc);
    cudaGetSymbolAddress((void**)&p_outc, g_outc);
    cudaGetSymbolAddress((void**)&p_ffn, g_ffn);
    cudaGetSymbolAddress((void**)&p_logits, g_logits);
    cudaGetSymbolAddress((void**)&p_qkv, g_qkv);

    // one-time side stream + events (R4-proven capture mechanism)
    static cudaStream_t s_copy = nullptr;
    static cudaEvent_t ev_fork = nullptr, ev_join = nullptr;
    if (!s_copy) {
        cudaStreamCreateWithFlags(&s_copy, cudaStreamNonBlocking);
        cudaEventCreateWithFlags(&ev_fork, cudaEventDisableTiming);
        cudaEventCreateWithFlags(&ev_join, cudaEventDisableTiming);
    }

    // cache copy forked to side stream, bounded to 40 SMs (grid-stride)
    cudaEventRecord(ev_fork, 0);
    cudaStreamWaitEvent(s_copy, ev_fork, 0);
    k_copy_p<<<40, 1024, 0, s_copy>>>((const float4*)ck, (const float4*)cv,
                                      (float4*)nk, (float4*)nv, stepp);
    cudaEventRecord(ev_join, s_copy);

    k_init<<<1, 1024>>>(input_id, stepp, tok, pos);

    for (int l = 0; l < L; l++) {
        size_t o = (size_t)l * H * H;
        size_t o1 = (size_t)l * H * FFN;
        size_t o2 = (size_t)l * FFN * H;
        // self-attention
        k_gemv3_ln<<<dim3(12, 64), 256>>>(Wq + o, Wk + o, Wv + o, ln1g + l * H, ln1b + l * H);
        k_attn_part<<<dim3(16, CH), 256>>>(ck, cv, nk, nv, stepp, l);
        k_gemv_merge<<<dim3(4, 64), 256>>>(Wo + o, p_x);   // fused merge + Wo; zeros qc
        // cross-attention (algebraically refactored)
        k_gemv_ln<<<dim3(4, 64), 256>>>(Cq + o, ln2g + l * H, ln2b + l * H, p_qc, H);
        k_U<<<128, 256>>>(Ck + o);
        k_scores<<<188, 512>>>(enc, cmask);
        k_softmax16<<<16, 256>>>();
        k_wsum<<<dim3(4, 32), 256>>>(enc);
        k_outc<<<128, 256>>>(Cv + o);
        k_gemv_plain<<<dim3(4, 64), 256>>>(Co + o, p_outc, p_x, H, 0, nullptr, 0, nullptr, 0);
        // FFN
        k_gemv_ln<<<dim3(16, 64), 256>>>(W1 + o1, ln3g + l * H, ln3b + l * H, p_ffn, FFN);
        k_gemv_plain<<<dim3(4, 256), 256>>>(W2 + o2, p_ffn, p_x, H, 1,
                                            p_qkv, 3 * H, p_logits, VOCAB);
    }
    // final projection + log-softmax
    k_gemv_ln<<<dim3(32, 64), 256>>>(Wout, lnfg, lnfb, p_logits, VOCAB);
    k_logsoftmax<<<1, 256>>>(out);

    cudaStreamWaitEvent(0, ev_join, 0);
}

// round 8
// speedup vs baseline: 1.7202x; 1.1209x over previous
#include <cuda_runtime.h>
#include <cuda_bf16.h>
#include <math.h>

#define L     8
#define NH    16
#define DH    64
#define SMAX  2048
#define H     1024
#define FFN   4096
#define ENC   1500
#define VOCAB 8192
#define FCH   48
#define CH    32   // attention key chunks

// ---------------- device state ----------------
__device__ __align__(16) float g_x[H];
__device__ __align__(16) float g_qkv[3 * H];
__device__ __align__(16) float g_qc[H];
__device__ __align__(16) float g_U[NH * H];
__device__ __align__(16) float g_sc[NH * ENC];
__device__ __align__(16) float g_W[NH * H];
__device__ __align__(16) float g_outc[H];
__device__ __align__(16) float g_ffn[FFN];
__device__ __align__(16) float g_logits[VOCAB];
__device__ float g_pm[NH * CH];
__device__ float g_ps[NH * CH];
__device__ __align__(16) float g_po[NH * CH * DH];
__device__ int   g_step_fallback[1] = {512};

// ---------------- PDL helpers ----------------
__device__ __forceinline__ void pdl_trigger() {
#if defined(__CUDA_ARCH__) && __CUDA_ARCH__ >= 900
    cudaTriggerProgrammaticLaunchCompletion();
#endif
}
__device__ __forceinline__ void pdl_sync() {
#if defined(__CUDA_ARCH__) && __CUDA_ARCH__ >= 900
    cudaGridDependencySynchronize();
#endif
}

// ---------------- block reductions ----------------
__device__ __forceinline__ float br_sum(float v, float* sb) {
    int tid = threadIdx.x, lane = tid & 31, w = tid >> 5;
#pragma unroll
    for (int o = 16; o; o >>= 1) v += __shfl_down_sync(0xffffffffu, v, o);
    if (lane == 0) sb[w] = v;
    __syncthreads();
    if (tid < 32) {
        int nw = (blockDim.x + 31) >> 5;
        float x = (tid < nw) ? sb[tid] : 0.0f;
#pragma unroll
        for (int o = 16; o; o >>= 1) x += __shfl_down_sync(0xffffffffu, x, o);
        if (tid == 0) sb[0] = x;
    }
    __syncthreads();
    float r = sb[0];
    __syncthreads();
    return r;
}

__device__ __forceinline__ float br_max(float v, float* sb) {
    int tid = threadIdx.x, lane = tid & 31, w = tid >> 5;
#pragma unroll
    for (int o = 16; o; o >>= 1) v = fmaxf(v, __shfl_down_sync(0xffffffffu, v, o));
    if (lane == 0) sb[w] = v;
    __syncthreads();
    if (tid < 32) {
        int nw = (blockDim.x + 31) >> 5;
        float x = (tid < nw) ? sb[tid] : -1e30f;
#pragma unroll
        for (int o = 16; o; o >>= 1) x = fmaxf(x, __shfl_down_sync(0xffffffffu, x, o));
        if (tid == 0) sb[0] = x;
    }
    __syncthreads();
    float r = sb[0];
    __syncthreads();
    return r;
}

__device__ __forceinline__ void ln_stats(float* sb, float& mean, float& rstd) {
    int tid = threadIdx.x;
    float s = 0.f;
    for (int i = tid; i < H; i += blockDim.x) s += g_x[i];
    mean = br_sum(s, sb) * (1.0f / H);
    float v = 0.f;
    for (int i = tid; i < H; i += blockDim.x) { float d = g_x[i] - mean; v += d * d; }
    rstd = rsqrtf(br_sum(v, sb) * (1.0f / H) + 1e-5f);
}

// ---------------- kernels ----------------

// one-wave grid-stride cache copy (296 blocks => PDL trigger fires immediately;
// nothing downstream syncs on it => free-running overlap)
__global__ void k_copy_p(const float4* __restrict__ ck, const float4* __restrict__ cv,
                         float4* __restrict__ nk, float4* __restrict__ nv,
                         const int* __restrict__ stepp) {
    pdl_trigger();
    int step = stepp[0];
    const size_t half = (size_t)L * NH * SMAX * 16;
    const size_t total = 2 * half;
    size_t stride = (size_t)gridDim.x * blockDim.x;
    for (size_t idx = (size_t)blockIdx.x * blockDim.x + threadIdx.x; idx < total; idx += stride) {
        const float4* src; float4* dst; size_t pos;
        if (idx < half) { src = ck; dst = nk; pos = idx; }
        else            { src = cv; dst = nv; pos = idx - half; }
        int t = (int)((pos >> 4) & (SMAX - 1));
        if (t < step)      dst[pos] = src[pos];
        else if (t > step) dst[pos] = make_float4(0.f, 0.f, 0.f, 0.f);
    }
}

// x = tok+pos; zero qkv + logits (reads only stable inputs -> no sync)
__global__ void k_init(const int* __restrict__ idp, const int* __restrict__ stepp,
                       const float* __restrict__ tok, const float* __restrict__ pos) {
    pdl_trigger();
    int tid = threadIdx.x;  // 1024
    int id = idp[0], st = stepp[0];
    g_x[tid] = tok[(size_t)id * H + tid] + pos[(size_t)st * H + tid];
    for (int i = tid; i < 3 * H; i += 1024) g_qkv[i] = 0.f;
    for (int i = tid; i < VOCAB; i += 1024) g_logits[i] = 0.f;
}

// qkv += LN1(x) @ [Wq|Wk|Wv] (grid (12,64), 256); weight-prefetch before sync
__global__ void k_gemv3_ln(const float* __restrict__ Wq, const float* __restrict__ Wk,
                           const float* __restrict__ Wv,
                           const float* __restrict__ g, const float* __restrict__ b) {
    __shared__ float sb[32];
    __shared__ float hc[16];
    int tid = threadIdx.x;
    pdl_trigger();
    int i0 = blockIdx.y * 16;
    int j = blockIdx.x * 256 + tid;  // 0..3071
    const float* Wm = (j < H) ? Wq : ((j < 2 * H) ? Wk : Wv);
    int jj = j & (H - 1);
    float w[16];
#pragma unroll
    for (int r = 0; r < 16; r++) w[r] = Wm[(size_t)(i0 + r) * H + jj];
    pdl_sync();
    float mean, rstd;
    ln_stats(sb, mean, rstd);
    if (tid < 16) { int i = i0 + tid; hc[tid] = (g_x[i] - mean) * rstd * g[i] + b[i]; }
    __syncthreads();
    float acc = 0.f;
#pragma unroll
    for (int r = 0; r < 16; r++) acc += hc[r] * w[r];
    atomicAdd(&g_qkv[j], acc);
}

// out += LN(x; g,b) @ W  (grid: n_out/256 x 64, block 256); prefetch before sync
__global__ void k_gemv_ln(const float* __restrict__ Wm,
                          const float* __restrict__ g, const float* __restrict__ b,
                          float* __restrict__ out, int n_out) {
    __shared__ float sb[32];
    __shared__ float hc[16];
    int tid = threadIdx.x;
    pdl_trigger();
    int i0 = blockIdx.y * 16;
    int j = blockIdx.x * 256 + tid;
    float w[16];
#pragma unroll
    for (int r = 0; r < 16; r++) w[r] = Wm[(size_t)(i0 + r) * n_out + j];
    pdl_sync();
    float mean, rstd;
    ln_stats(sb, mean, rstd);
    if (tid < 16) { int i = i0 + tid; hc[tid] = (g_x[i] - mean) * rstd * g[i] + b[i]; }
    __syncthreads();
    float acc = 0.f;
#pragma unroll
    for (int r = 0; r < 16; r++) acc += hc[r] * w[r];
    atomicAdd(&out[j], acc);
}

// out += (relu?)a @ W; optional zero of one buffer; prefetch before sync
__global__ void k_gemv_plain(const float* __restrict__ Wm, const float* __restrict__ a,
                             float* __restrict__ out, int n_out, int relu,
                             float* z1, int zn1) {
    __shared__ float ac[16];
    int tid = threadIdx.x;
    pdl_trigger();
    int i0 = blockIdx.y * 16;
    int j = blockIdx.x * 256 + tid;
    float w[16];
#pragma unroll
    for (int r = 0; r < 16; r++) w[r] = Wm[(size_t)(i0 + r) * n_out + j];
    pdl_sync();
    if (zn1 > 0) {
        int gt = (blockIdx.y * gridDim.x + blockIdx.x) * 256 + tid;
        int T = gridDim.x * gridDim.y * 256;
        for (int k = gt; k < zn1; k += T) z1[k] = 0.f;
    }
    if (tid < 16) { float x = a[i0 + tid]; if (relu) x = fmaxf(x, 0.f); ac[tid] = x; }
    __syncthreads();
    float acc = 0.f;
#pragma unroll
    for (int r = 0; r < 16; r++) acc += ac[r] * w[r];
    atomicAdd(&out[j], acc);
}

// x += merge(attn partials) @ Wo (grid (4,64), 256); zeros g_qc; prefetch
__global__ void k_gemv_merge(const float* __restrict__ Wm) {
    __shared__ float ac[16];
    int tid = threadIdx.x;
    pdl_trigger();
    int i0 = blockIdx.y * 16;
    int j = blockIdx.x * 256 + tid;
    float w[16];
#pragma unroll
    for (int r = 0; r < 16; r++) w[r] = Wm[(size_t)(i0 + r) * H + j];
    pdl_sync();
    int gt = (blockIdx.y * gridDim.x + blockIdx.x) * 256 + tid;
    int T = gridDim.x * gridDim.y * 256;
    for (int k = gt; k < H; k += T) g_qc[k] = 0.f;
    if (tid < 16) {
        int i = i0 + tid;
        int h = i >> 6, d = i & 63;
        float M = -1e30f;
#pragma unroll
        for (int c = 0; c < CH; c++) M = fmaxf(M, g_pm[h * CH + c]);
        float S = 0.f, o = 0.f;
#pragma unroll
        for (int c = 0; c < CH; c++) {
            float e = __expf(g_pm[h * CH + c] - M);
            S += g_ps[h * CH + c] * e;
            o += e * g_po[(h * CH + c) * 64 + d];
        }
        ac[tid] = o / S;
    }
    __syncthreads();
    float acc = 0.f;
#pragma unroll
    for (int r = 0; r < 16; r++) acc += ac[r] * w[r];
    atomicAdd(&g_x[j], acc);
}

// flash-decode partials (R5-proven warp-per-key, grid (16,32), block 128)
__global__ void k_attn_part(const float* __restrict__ ck, const float* __restrict__ cv,
                            float* __restrict__ nk, float* __restrict__ nv,
                            const int* __restrict__ stepp, int l) {
    __shared__ float2 q2[32];
    __shared__ float sc[72];
    __shared__ float sb[32];
    __shared__ float2 red2[128];
    int tid = threadIdx.x;
    pdl_trigger();
    pdl_sync();
    int h = blockIdx.x, c = blockIdx.y;
    int step = stepp[0];
    int n = step + 1;
    int cs = (n + CH - 1) / CH;
    int k0 = c * cs;
    int k1 = min(n, k0 + cs);
    int cnt = k1 - k0;
    int w = tid >> 5, lane = tid & 31;
    if (tid < 32) q2[tid] = ((const float2*)&g_qkv[h * 64])[tid];
    __syncthreads();
    float2 q = q2[lane];
    const float* kbase = ck + (size_t)(l * NH + h) * SMAX * DH;
    for (int kk = k0 + w; kk < k1; kk += 4) {
        const float2* kp = (kk < step) ? (const float2*)(kbase + (size_t)kk * DH)
                                       : (const float2*)(&g_qkv[H + h * 64]);
        float2 kv = kp[lane];
        float v = kv.x * q.x + kv.y * q.y;
#pragma unroll
        for (int o = 16; o; o >>= 1) v += __shfl_down_sync(0xffffffffu, v, o);
        if (lane == 0) sc[kk - k0] = v * 0.125f;
    }
    __syncthreads();
    float m = -1e30f;
    for (int i = tid; i < cnt; i += 128) m = fmaxf(m, sc[i]);
    m = br_max(m, sb);
    float s = 0.f;
    for (int i = tid; i < cnt; i += 128) { float e = __expf(sc[i] - m); sc[i] = e; s += e; }
    s = br_sum(s, sb);
    const float* vbase = cv + (size_t)(l * NH + h) * SMAX * DH;
    float2 acc = make_float2(0.f, 0.f);
    for (int kk = k0 + w; kk < k1; kk += 4) {
        const float2* vp = (kk < step) ? (const float2*)(vbase + (size_t)kk * DH)
                                       : (const float2*)(&g_qkv[2 * H + h * 64]);
        float wgt = sc[kk - k0];
        float2 v = vp[lane];
        acc.x += wgt * v.x; acc.y += wgt * v.y;
    }
    red2[tid] = acc;
    __syncthreads();
    if (w == 0) {
        float2 o;
        o.x = red2[lane].x + red2[32 + lane].x + red2[64 + lane].x + red2[96 + lane].x;
        o.y = red2[lane].y + red2[32 + lane].y + red2[64 + lane].y + red2[96 + lane].y;
        g_po[(h * CH + c) * 64 + 2 * lane]     = o.x;
        g_po[(h * CH + c) * 64 + 2 * lane + 1] = o.y;
        if (lane == 0) { g_pm[h * CH + c] = m; g_ps[h * CH + c] = s; }
    }
    if (c == 0 && tid >= 64) {  // write new k/v slot (t == step; disjoint from copy)
        int t2 = tid - 64;
        size_t base = ((size_t)(l * NH + h) * SMAX + step) * DH;
        if (t2 < 32) ((float2*)(nk + base))[t2]      = ((const float2*)(g_qkv + H + h * 64))[t2];
        else         ((float2*)(nv + base))[t2 - 32] = ((const float2*)(g_qkv + 2 * H + h * 64))[t2 - 32];
    }
}

// U[h][i]: grid 128, block 256 (R3-proven)
__global__ void k_U(const float* __restrict__ Ck) {
    __shared__ float4 qs[256];
    int tid = threadIdx.x;
    pdl_trigger();
    pdl_sync();
    qs[tid] = ((const float4*)g_qc)[tid];
    __syncthreads();
    float4 q = qs[tid];
    int i0 = blockIdx.x * 8;
    int h = tid >> 4;
#pragma unroll
    for (int r = 0; r < 8; r++) {
        int i = i0 + r;
        float4 w = ((const float4*)(Ck + (size_t)i * H))[tid];
        float v = w.x * q.x + w.y * q.y + w.z * q.z + w.w * q.w;
        v += __shfl_down_sync(0xffffffffu, v, 8);
        v += __shfl_down_sync(0xffffffffu, v, 4);
        v += __shfl_down_sync(0xffffffffu, v, 2);
        v += __shfl_down_sync(0xffffffffu, v, 1);
        if ((tid & 15) == 0) g_U[h * H + i] = v;
    }
}

// scores: grid 188, block 512 (R3-proven)
__global__ void k_scores(const float* __restrict__ enc, const float* __restrict__ cmask) {
    pdl_trigger();
    pdl_sync();
    int w = threadIdx.x >> 5, lane = threadIdx.x & 31;
    const float4* up = (const float4*)(g_U + w * H);
    float4 u[8];
#pragma unroll
    for (int j = 0; j < 8; j++) u[j] = up[lane + 32 * j];
#pragma unroll
    for (int ff = 0; ff < 8; ff++) {
        int f = blockIdx.x * 8 + ff;
        if (f >= ENC) break;
        const float4* ep = (const float4*)(enc + (size_t)f * H);
        float acc = 0.f;
#pragma unroll
        for (int j = 0; j < 8; j++) {
            float4 e = ep[lane + 32 * j];
            acc += e.x * u[j].x + e.y * u[j].y + e.z * u[j].z + e.w * u[j].w;
        }
#pragma unroll
        for (int o = 16; o; o >>= 1) acc += __shfl_down_sync(0xffffffffu, acc, o);
        if (lane == 0) g_sc[w * ENC + f] = acc * 0.125f + cmask[f];
    }
}

// per-head softmax; zero g_W and g_outc. grid 16, block 256 (R3-proven)
__global__ void k_softmax16() {
    __shared__ float sb[32];
    int tid = threadIdx.x;
    pdl_trigger();
    pdl_sync();
    int h = blockIdx.x;
    float* row = &g_sc[h * ENC];
    float m = -1e30f;
    for (int i = tid; i < ENC; i += 256) m = fmaxf(m, row[i]);
    m = br_max(m, sb);
    float s = 0.f;
    for (int i = tid; i < ENC; i += 256) { float e = __expf(row[i] - m); row[i] = e; s += e; }
    s = br_sum(s, sb);
    float inv = 1.f / s;
    for (int i = tid; i < ENC; i += 256) row[i] *= inv;
    for (int i = tid; i < H; i += 256) g_W[h * H + i] = 0.f;
    if (h == 0) for (int i = tid; i < H; i += 256) g_outc[i] = 0.f;
}

// W[h][cols] += attc @ enc. grid (4,32), block 256 (R3-proven)
__global__ void k_wsum(const float* __restrict__ enc) {
    __shared__ float at[4 * FCH];
    int tid = threadIdx.x, fc = blockIdx.y, hg = blockIdx.x;
    pdl_trigger();
    pdl_sync();
    for (int idx = tid; idx < 4 * FCH; idx += 256) {
        int hh = idx / FCH, k = idx % FCH;
        int f = fc * FCH + k;
        at[idx] = (f < ENC) ? g_sc[(hg * 4 + hh) * ENC + f] : 0.f;
    }
    __syncthreads();
    int c0 = tid * 4;
    float4 acc[4];
#pragma unroll
    for (int hh = 0; hh < 4; hh++) acc[hh] = make_float4(0.f, 0.f, 0.f, 0.f);
    int fend = min(FCH, ENC - fc * FCH);
    for (int k = 0; k < fend; k++) {
        float4 e = *(const float4*)(enc + (size_t)(fc * FCH + k) * H + c0);
#pragma unroll
        for (int hh = 0; hh < 4; hh++) {
            float a = at[hh * FCH + k];
            acc[hh].x += a * e.x; acc[hh].y += a * e.y;
            acc[hh].z += a * e.z; acc[hh].w += a * e.w;
        }
    }
#pragma unroll
    for (int hh = 0; hh < 4; hh++) {
        float* o = &g_W[(hg * 4 + hh) * H + c0];
        atomicAdd(o, acc[hh].x); atomicAdd(o + 1, acc[hh].y);
        atomicAdd(o + 2, acc[hh].z); atomicAdd(o + 3, acc[hh].w);
    }
}

// outc[col] += sum_i W[h(col),i]*Cv[i,col]; zero g_ffn. grid 128, block 256 (R3-proven)
__global__ void k_outc(const float* __restrict__ Cv) {
    int tid = threadIdx.x;
    pdl_trigger();
    pdl_sync();
    int c0 = tid * 4;
    int h = tid >> 4;
    int i0 = blockIdx.x * 8;
    float4 acc = make_float4(0.f, 0.f, 0.f, 0.f);
#pragma unroll
    for (int r = 0; r < 8; r++) {
        int i = i0 + r;
        float wv = g_W[h * H + i];
        float4 cv4 = *(const float4*)(Cv + (size_t)i * H + c0);
        acc.x += wv * cv4.x; acc.y += wv * cv4.y;
        acc.z += wv * cv4.z; acc.w += wv * cv4.w;
    }
    float* o = &g_outc[c0];
    atomicAdd(o, acc.x); atomicAdd(o + 1, acc.y);
    atomicAdd(o + 2, acc.z); atomicAdd(o + 3, acc.w);
    int gt = blockIdx.x * 256 + tid;
    if (gt < FFN) g_ffn[gt] = 0.f;
}

__global__ void k_logsoftmax(float* __restrict__ out) {
    __shared__ float sb[32];
    int tid = threadIdx.x;
    pdl_trigger();
    pdl_sync();
    float m = -1e30f;
    for (int i = tid; i < VOCAB; i += 256) m = fmaxf(m, g_logits[i]);
    m = br_max(m, sb);
    float s = 0.f;
    for (int i = tid; i < VOCAB; i += 256) s += __expf(g_logits[i] - m);
    s = br_sum(s, sb);
    float ls = logf(s);
    for (int i = tid; i < VOCAB; i += 256) out[i] = g_logits[i] - m - ls;
}

// ---------------- host ----------------
template <typename... Args>
static inline void lp(void (*k)(Args...), dim3 g, dim3 b, Args... a) {
    cudaLaunchConfig_t cfg = {};
    cfg.gridDim = g; cfg.blockDim = b;
    cfg.dynamicSmemBytes = 0; cfg.stream = 0;
    cudaLaunchAttribute at[1];
    at[0].id = cudaLaunchAttributeProgrammaticStreamSerialization;
    at[0].val.programmaticStreamSerializationAllowed = 1;
    cfg.attrs = at; cfg.numAttrs = 1;
    cudaLaunchKernelEx(&cfg, k, a...);
}

extern "C" void kernel_launch(void* const* d_in, const int* in_sizes, int n_in,
                              void* d_out, int out_size) {
    int has_step = (n_in >= 27) ? 1 : 0;
    int idx = 0;
    const int*   input_id = (const int*)d_in[idx++];
    const float* enc      = (const float*)d_in[idx++];
    const float* ck       = (const float*)d_in[idx++];
    const float* cv       = (const float*)d_in[idx++];
    const int*   stepp    = nullptr;
    if (has_step) stepp = (const int*)d_in[idx++];
    const float* cmask = (const float*)d_in[idx++];
    const float* tok   = (const float*)d_in[idx++];
    const float* pos   = (const float*)d_in[idx++];
    const float* Wq = (const float*)d_in[idx++];
    const float* Wk = (const float*)d_in[idx++];
    const float* Wv = (const float*)d_in[idx++];
    const float* Wo = (const float*)d_in[idx++];
    const float* Cq = (const float*)d_in[idx++];
    const float* Ck = (const float*)d_in[idx++];
    const float* Cv = (const float*)d_in[idx++];
    const float* Co = (const float*)d_in[idx++];
    const float* W1 = (const float*)d_in[idx++];
    const float* W2 = (const float*)d_in[idx++];
    const float* ln1g = (const float*)d_in[idx++];
    const float* ln1b = (const float*)d_in[idx++];
    const float* ln2g = (const float*)d_in[idx++];
    const float* ln2b = (const float*)d_in[idx++];
    const float* ln3g = (const float*)d_in[idx++];
    const float* ln3b = (const float*)d_in[idx++];
    const float* lnfg = (const float*)d_in[idx++];
    const float* lnfb = (const float*)d_in[idx++];
    const float* Wout = (const float*)d_in[idx++];

    if (!stepp) {
        void* p;
        cudaGetSymbolAddress(&p, g_step_fallback);
        stepp = (const int*)p;
    }

    float* out = (float*)d_out;
    float* nk = out + VOCAB;
    float* nv = nk + (size_t)L * NH * SMAX * DH;

    float *p_qc, *p_outc, *p_ffn, *p_logits, *p_qkv, *p_x;
    cudaGetSymbolAddress((void**)&p_x, g_x);
    cudaGetSymbolAddress((void**)&p_qc, g_qc);
    cudaGetSymbolAddress((void**)&p_outc, g_outc);
    cudaGetSymbolAddress((void**)&p_ffn, g_ffn);
    cudaGetSymbolAddress((void**)&p_logits, g_logits);
    cudaGetSymbolAddress((void**)&p_qkv, g_qkv);

    // cache copy: one wave; successors never gridDepSync on it -> free overlap
    lp(k_copy_p, dim3(296), dim3(1024),
       (const float4*)ck, (const float4*)cv, (float4*)nk, (float4*)nv, stepp);
    lp(k_init, dim3(1), dim3(1024), input_id, stepp, tok, pos);

    for (int l = 0; l < L; l++) {
        size_t o = (size_t)l * H * H;
        size_t o1 = (size_t)l * H * FFN;
        size_t o2 = (size_t)l * FFN * H;
        // self-attention
        lp(k_gemv3_ln, dim3(12, 64), dim3(256), Wq + o, Wk + o, Wv + o,
           (const float*)(ln1g + l * H), (const float*)(ln1b + l * H));
        lp(k_attn_part, dim3(16, CH), dim3(128), ck, cv, nk, nv, stepp, l);
        lp(k_gemv_merge, dim3(4, 64), dim3(256), Wo + o);
        // cross-attention (algebraically refactored)
        lp(k_gemv_ln, dim3(4, 64), dim3(256), Cq + o,
           (const float*)(ln2g + l * H), (const float*)(ln2b + l * H), p_qc, H);
        lp(k_U, dim3(128), dim3(256), Ck + o);
        lp(k_scores, dim3(188), dim3(512), enc, cmask);
        lp(k_softmax16, dim3(16), dim3(256));
        lp(k_wsum, dim3(4, 32), dim3(256), enc);
        lp(k_outc, dim3(128), dim3(256), Cv + o);
        lp(k_gemv_plain, dim3(4, 64), dim3(256), Co + o, (const float*)p_outc, p_x, H, 0,
           (float*)nullptr, 0);
        // FFN
        lp(k_gemv_ln, dim3(16, 64), dim3(256), W1 + o1,
           (const float*)(ln3g + l * H), (const float*)(ln3b + l * H), p_ffn, FFN);
        lp(k_gemv_plain, dim3(4, 256), dim3(256), W2 + o2, (const float*)p_ffn, p_x, H, 1,
           p_qkv, 3 * H);
    }
    // final projection + log-softmax
    lp(k_gemv_ln, dim3(32, 64), dim3(256), Wout, lnfg, lnfb, p_logits, VOCAB);
    lp(k_logsoftmax, dim3(1), dim3(256), out);
}